// round 7
// baseline (speedup 1.0000x reference)
#include <cuda_runtime.h>
#include <cuda_bf16.h>
#include <math.h>
#include <cstdint>

// Problem constants
#define NB   32      // batch
#define SL   256     // sequence length
#define DD   1024    // input dim
#define HH   1024    // hidden dim
#define NBLK 128     // persistent blocks (64 col-tiles * 2 dir)

// ---------------------------------------------------------------------------
// Scratch (device globals)
// ---------------------------------------------------------------------------
__device__ float g_xh[(size_t)8 * SL * NB * HH];   // 268 MB: xh[g][s][n][h]
__device__ float g_pre[2][4][NB][HH];              // pre-activations (recurrent part)
__device__ int   g_bar[2][SL];                     // grid barrier counters
// bf16 split operands for the input GEMM
__device__ __nv_bfloat16 g_xa_hi[(size_t)NB * SL * DD];
__device__ __nv_bfloat16 g_xa_lo[(size_t)NB * SL * DD];
__device__ __nv_bfloat16 g_wt_hi[(size_t)8 * HH * DD];   // W_ih [g][n][k]
__device__ __nv_bfloat16 g_wt_lo[(size_t)8 * HH * DD];
// bf16 split operands for the recurrence
__device__ __nv_bfloat16 g_wr_hi[(size_t)8 * HH * DD];   // W_hh [g][n][k]
__device__ __nv_bfloat16 g_wr_lo[(size_t)8 * HH * DD];
__device__ __nv_bfloat16 g_hbf_hi[2][NB][HH];            // h state bf16 hi
__device__ __nv_bfloat16 g_hbf_lo[2][NB][HH];            // h state bf16 lo

__device__ __forceinline__ float sigmf(float v) {
    return 1.0f / (1.0f + expf(-v));
}

// mma.sync m16n8k16 bf16, fp32 accumulate
__device__ __forceinline__ void mma16816(float* c, const uint32_t* a,
                                         const uint32_t* b) {
    asm volatile(
        "mma.sync.aligned.m16n8k16.row.col.f32.bf16.bf16.f32 "
        "{%0,%1,%2,%3}, {%4,%5,%6,%7}, {%8,%9}, {%0,%1,%2,%3};"
        : "+f"(c[0]), "+f"(c[1]), "+f"(c[2]), "+f"(c[3])
        : "r"(a[0]), "r"(a[1]), "r"(a[2]), "r"(a[3]), "r"(b[0]), "r"(b[1]));
}

// ---------------------------------------------------------------------------
// Kernel 0: zero init of bf16 h state and barrier counters
// ---------------------------------------------------------------------------
__global__ void zero_state_kernel() {
    int idx = blockIdx.x * blockDim.x + threadIdx.x;
    // 2*NB*HH bf16 each = 2*32*1024*2B; zero as floats (32768 each)
    float* h1 = (float*)&g_hbf_hi[0][0][0];
    float* h2 = (float*)&g_hbf_lo[0][0][0];
    int total = 2 * NB * HH / 2;
    for (int i = idx; i < total; i += gridDim.x * blockDim.x) {
        h1[i] = 0.0f;
        h2[i] = 0.0f;
    }
    int* bar = &g_bar[0][0];
    for (int i = idx; i < 2 * SL; i += gridDim.x * blockDim.x) bar[i] = 0;
}

// ---------------------------------------------------------------------------
// Kernel A: convert x -> bf16 hi/lo   (rows r = n*SL+s, cols d)
// ---------------------------------------------------------------------------
__global__ __launch_bounds__(256)
void convert_x_kernel(const float* __restrict__ x) {
    const size_t total4 = (size_t)NB * SL * DD / 4;
    for (size_t i = blockIdx.x * 256 + threadIdx.x; i < total4;
         i += (size_t)gridDim.x * 256) {
        float4 v = *(const float4*)(x + i * 4);
        __nv_bfloat16 h0 = __float2bfloat16_rn(v.x);
        __nv_bfloat16 h1 = __float2bfloat16_rn(v.y);
        __nv_bfloat16 h2 = __float2bfloat16_rn(v.z);
        __nv_bfloat16 h3 = __float2bfloat16_rn(v.w);
        __nv_bfloat16 l0 = __float2bfloat16_rn(v.x - __bfloat162float(h0));
        __nv_bfloat16 l1 = __float2bfloat16_rn(v.y - __bfloat162float(h1));
        __nv_bfloat16 l2 = __float2bfloat16_rn(v.z - __bfloat162float(h2));
        __nv_bfloat16 l3 = __float2bfloat16_rn(v.w - __bfloat162float(h3));
        __nv_bfloat162 hh0 = __halves2bfloat162(h0, h1);
        __nv_bfloat162 hh1 = __halves2bfloat162(h2, h3);
        __nv_bfloat162 ll0 = __halves2bfloat162(l0, l1);
        __nv_bfloat162 ll1 = __halves2bfloat162(l2, l3);
        *(uint2*)(g_xa_hi + i * 4) = make_uint2(
            *(uint32_t*)&hh0, *(uint32_t*)&hh1);
        *(uint2*)(g_xa_lo + i * 4) = make_uint2(
            *(uint32_t*)&ll0, *(uint32_t*)&ll1);
    }
}

// ---------------------------------------------------------------------------
// Kernel B: transpose + convert weights -> wt[g][n][k] bf16 hi/lo
// which = 0 -> W_ih into g_wt_*, which = 1 -> W_hh into g_wr_*
// ---------------------------------------------------------------------------
__global__ void convert_w_kernel(const float* __restrict__ w, int which) {
    __shared__ float tile[32][33];
    const int g  = blockIdx.z;
    const int k0 = blockIdx.x * 32;
    const int n0 = blockIdx.y * 32;
    const int tx = threadIdx.x, ty = threadIdx.y;   // (32, 8)
    const float* W = w + ((size_t)g << 20);
    __nv_bfloat16* dst_hi = which ? g_wr_hi : g_wt_hi;
    __nv_bfloat16* dst_lo = which ? g_wr_lo : g_wt_lo;
#pragma unroll
    for (int i = 0; i < 4; i++)
        tile[ty + 8 * i][tx] = W[(size_t)(k0 + ty + 8 * i) * HH + n0 + tx];
    __syncthreads();
#pragma unroll
    for (int i = 0; i < 4; i++) {
        float v = tile[tx][ty + 8 * i];     // = W[k0+tx][n0+ty+8i]
        __nv_bfloat16 hi = __float2bfloat16_rn(v);
        __nv_bfloat16 lo = __float2bfloat16_rn(v - __bfloat162float(hi));
        size_t idx = ((size_t)g << 20) + (size_t)(n0 + ty + 8 * i) * DD + k0 + tx;
        dst_hi[idx] = hi;
        dst_lo[idx] = lo;
    }
}

// ---------------------------------------------------------------------------
// Kernel C: mma.sync bf16x3 input-projection GEMM (unchanged from R6).
// CTA tile 128(m) x 64(n), 8 warps (warp tile 32x32), K-chunk 32.
// ---------------------------------------------------------------------------
#define ASTR 40   // smem k-stride for conflict-free frag loads

__global__ __launch_bounds__(256, 2)
void gemm_ih_mma_kernel(const float* __restrict__ bias) {
    __shared__ __nv_bfloat16 As_hi[128][ASTR];
    __shared__ __nv_bfloat16 As_lo[128][ASTR];
    __shared__ __nv_bfloat16 Bs_hi[64][ASTR];
    __shared__ __nv_bfloat16 Bs_lo[64][ASTR];

    const int g   = blockIdx.z;
    const int m0  = blockIdx.x * 128;
    const int n0  = blockIdx.y * 64;
    const int tid = threadIdx.x;
    const int wid = tid >> 5;
    const int lid = tid & 31;
    const int wm  = wid & 3;
    const int wn  = wid >> 2;

    const __nv_bfloat16* a_hi = g_xa_hi;
    const __nv_bfloat16* a_lo = g_xa_lo;
    const __nv_bfloat16* b_hi = g_wt_hi + ((size_t)g << 20);
    const __nv_bfloat16* b_lo = g_wt_lo + ((size_t)g << 20);

    float acc[2][4][4];
#pragma unroll
    for (int mt = 0; mt < 2; mt++)
#pragma unroll
        for (int nt = 0; nt < 4; nt++)
#pragma unroll
            for (int r = 0; r < 4; r++) acc[mt][nt][r] = 0.0f;

    const int fq = lid >> 2;
    const int fk = (lid & 3) * 2;

    for (int k0 = 0; k0 < DD; k0 += 32) {
        __syncthreads();
#pragma unroll
        for (int s = 0; s < 2; s++) {
            int lin = tid + s * 256;
            int row = lin >> 2;
            int kq  = (lin & 3) * 8;
            *(uint4*)&As_hi[row][kq] =
                *(const uint4*)(a_hi + (size_t)(m0 + row) * DD + k0 + kq);
            *(uint4*)&As_lo[row][kq] =
                *(const uint4*)(a_lo + (size_t)(m0 + row) * DD + k0 + kq);
        }
        {
            int row = tid >> 2;
            int kq  = (tid & 3) * 8;
            *(uint4*)&Bs_hi[row][kq] =
                *(const uint4*)(b_hi + (size_t)(n0 + row) * DD + k0 + kq);
            *(uint4*)&Bs_lo[row][kq] =
                *(const uint4*)(b_lo + (size_t)(n0 + row) * DD + k0 + kq);
        }
        __syncthreads();

#pragma unroll
        for (int ks = 0; ks < 32; ks += 16) {
            uint32_t Ah[2][4], Al[2][4], Bh[4][2], Bl[4][2];
#pragma unroll
            for (int mt = 0; mt < 2; mt++) {
                int mb = wm * 32 + mt * 16;
                Ah[mt][0] = *(const uint32_t*)&As_hi[mb + fq][ks + fk];
                Ah[mt][1] = *(const uint32_t*)&As_hi[mb + fq + 8][ks + fk];
                Ah[mt][2] = *(const uint32_t*)&As_hi[mb + fq][ks + fk + 8];
                Ah[mt][3] = *(const uint32_t*)&As_hi[mb + fq + 8][ks + fk + 8];
                Al[mt][0] = *(const uint32_t*)&As_lo[mb + fq][ks + fk];
                Al[mt][1] = *(const uint32_t*)&As_lo[mb + fq + 8][ks + fk];
                Al[mt][2] = *(const uint32_t*)&As_lo[mb + fq][ks + fk + 8];
                Al[mt][3] = *(const uint32_t*)&As_lo[mb + fq + 8][ks + fk + 8];
            }
#pragma unroll
            for (int nt = 0; nt < 4; nt++) {
                int nb = wn * 32 + nt * 8;
                Bh[nt][0] = *(const uint32_t*)&Bs_hi[nb + fq][ks + fk];
                Bh[nt][1] = *(const uint32_t*)&Bs_hi[nb + fq][ks + fk + 8];
                Bl[nt][0] = *(const uint32_t*)&Bs_lo[nb + fq][ks + fk];
                Bl[nt][1] = *(const uint32_t*)&Bs_lo[nb + fq][ks + fk + 8];
            }
#pragma unroll
            for (int mt = 0; mt < 2; mt++)
#pragma unroll
                for (int nt = 0; nt < 4; nt++) {
                    mma16816(acc[mt][nt], Ah[mt], Bh[nt]);
                    mma16816(acc[mt][nt], Ah[mt], Bl[nt]);
                    mma16816(acc[mt][nt], Al[mt], Bh[nt]);
                }
        }
    }

#pragma unroll
    for (int mt = 0; mt < 2; mt++) {
#pragma unroll
        for (int nt = 0; nt < 4; nt++) {
            int col = n0 + wn * 32 + nt * 8 + (lid & 3) * 2;
            float2 bz = *(const float2*)&bias[g * HH + col];
#pragma unroll
            for (int half = 0; half < 2; half++) {
                int row  = m0 + wm * 32 + mt * 16 + fq + half * 8;
                int nidx = row >> 8;
                int s    = row & 255;
                size_t base = ((((size_t)g * SL + s) * NB + nidx) << 10) + col;
                *(float2*)&g_xh[base] = make_float2(
                    acc[mt][nt][half * 2 + 0] + bz.x,
                    acc[mt][nt][half * 2 + 1] + bz.y);
            }
        }
    }
}

// ---------------------------------------------------------------------------
// Kernel D: persistent fused recurrence on tensor cores.
// 128 blocks x 128 threads. Block -> (dir, 64-col tile). Warp tile 32m x 16n.
// Per step: GEMM (bf16x3 mma over K=1024) -> barrier -> cell -> barrier.
// ---------------------------------------------------------------------------
#define RSTR 72   // smem k-stride (64 + 8) for conflict-free frag loads

__global__ __launch_bounds__(128)
void bilstm_persistent_mma(const float* __restrict__ mask,
                           float* __restrict__ out) {
    __shared__ __nv_bfloat16 As_hi[32][RSTR];
    __shared__ __nv_bfloat16 As_lo[32][RSTR];
    __shared__ __nv_bfloat16 Bs_hi[64][RSTR];
    __shared__ __nv_bfloat16 Bs_lo[64][RSTR];

    const int bid = blockIdx.x;
    const int dir = bid & 1;
    const int ct  = bid >> 1;              // 0..63
    const int tid = threadIdx.x;
    const int wid = tid >> 5;
    const int lid = tid & 31;

    const int col0 = ct * 64;
    const int gate = col0 >> 10;
    const int hcol = col0 & 1023;
    const __nv_bfloat16* Bg_hi =
        g_wr_hi + (((size_t)(dir * 4 + gate)) << 20) + (size_t)hcol * DD;
    const __nv_bfloat16* Bg_lo =
        g_wr_lo + (((size_t)(dir * 4 + gate)) << 20) + (size_t)hcol * DD;
    const __nv_bfloat16* Ag_hi = &g_hbf_hi[dir][0][0];
    const __nv_bfloat16* Ag_lo = &g_hbf_lo[dir][0][0];

    const int fq = lid >> 2;
    const int fk = (lid & 3) * 2;

    // Cell assignment: idx -> (dir_c, n_c, 4 h cols)
    const int cidx  = bid * 128 + tid;       // 0..16383
    const int dir_c = cidx >> 13;
    const int n_c   = (cidx >> 8) & 31;
    const int h_c   = (cidx & 255) * 4;
    float cc[4] = {0.f, 0.f, 0.f, 0.f};
    float hr[4] = {0.f, 0.f, 0.f, 0.f};
    const float* mrow = mask + n_c * SL;

    for (int t = 0; t < SL; t++) {
        const int pos_c = dir_c ? (SL - 1 - t) : t;

        // Prefetch cell xh + mask (hide DRAM latency under GEMM)
        float4 xpre[4];
#pragma unroll
        for (int g = 0; g < 4; ++g)
            xpre[g] = __ldcg((const float4*)&g_xh[
                ((((size_t)(dir_c * 4 + g) * SL + pos_c) * NB + n_c) << 10) + h_c]);
        const float m = mrow[pos_c];

        // ================= GEMM phase =================
        float acc[2][2][4];
#pragma unroll
        for (int mt = 0; mt < 2; mt++)
#pragma unroll
            for (int nt = 0; nt < 2; nt++)
#pragma unroll
                for (int r = 0; r < 4; r++) acc[mt][nt][r] = 0.0f;

        for (int k0 = 0; k0 < HH; k0 += 64) {
            __syncthreads();
            // A tiles: 32 rows x 64 k, 256 uint4 slots per array
#pragma unroll
            for (int s = 0; s < 2; s++) {
                int lin = tid + s * 128;
                int row = lin >> 3;
                int kq  = (lin & 7) * 8;
                *(uint4*)&As_hi[row][kq] =
                    __ldcg((const uint4*)(Ag_hi + (size_t)row * HH + k0 + kq));
                *(uint4*)&As_lo[row][kq] =
                    __ldcg((const uint4*)(Ag_lo + (size_t)row * HH + k0 + kq));
            }
            // B tiles: 64 rows x 64 k, 512 uint4 slots per array
#pragma unroll
            for (int s = 0; s < 4; s++) {
                int lin = tid + s * 128;
                int row = lin >> 3;
                int kq  = (lin & 7) * 8;
                *(uint4*)&Bs_hi[row][kq] =
                    *(const uint4*)(Bg_hi + (size_t)row * DD + k0 + kq);
                *(uint4*)&Bs_lo[row][kq] =
                    *(const uint4*)(Bg_lo + (size_t)row * DD + k0 + kq);
            }
            __syncthreads();

#pragma unroll
            for (int ks = 0; ks < 64; ks += 16) {
                uint32_t Ah[2][4], Al[2][4], Bh[2][2], Bl[2][2];
#pragma unroll
                for (int mt = 0; mt < 2; mt++) {
                    int mb = mt * 16;
                    Ah[mt][0] = *(const uint32_t*)&As_hi[mb + fq][ks + fk];
                    Ah[mt][1] = *(const uint32_t*)&As_hi[mb + fq + 8][ks + fk];
                    Ah[mt][2] = *(const uint32_t*)&As_hi[mb + fq][ks + fk + 8];
                    Ah[mt][3] = *(const uint32_t*)&As_hi[mb + fq + 8][ks + fk + 8];
                    Al[mt][0] = *(const uint32_t*)&As_lo[mb + fq][ks + fk];
                    Al[mt][1] = *(const uint32_t*)&As_lo[mb + fq + 8][ks + fk];
                    Al[mt][2] = *(const uint32_t*)&As_lo[mb + fq][ks + fk + 8];
                    Al[mt][3] = *(const uint32_t*)&As_lo[mb + fq + 8][ks + fk + 8];
                }
#pragma unroll
                for (int nt = 0; nt < 2; nt++) {
                    int nb = wid * 16 + nt * 8;
                    Bh[nt][0] = *(const uint32_t*)&Bs_hi[nb + fq][ks + fk];
                    Bh[nt][1] = *(const uint32_t*)&Bs_hi[nb + fq][ks + fk + 8];
                    Bl[nt][0] = *(const uint32_t*)&Bs_lo[nb + fq][ks + fk];
                    Bl[nt][1] = *(const uint32_t*)&Bs_lo[nb + fq][ks + fk + 8];
                }
#pragma unroll
                for (int mt = 0; mt < 2; mt++)
#pragma unroll
                    for (int nt = 0; nt < 2; nt++) {
                        mma16816(acc[mt][nt], Ah[mt], Bh[nt]);
                        mma16816(acc[mt][nt], Ah[mt], Bl[nt]);
                        mma16816(acc[mt][nt], Al[mt], Bh[nt]);
                    }
            }
        }

        // Write pre-activations: g_pre[dir][gate][row][hc]
#pragma unroll
        for (int mt = 0; mt < 2; mt++) {
#pragma unroll
            for (int nt = 0; nt < 2; nt++) {
                int hc = hcol + wid * 16 + nt * 8 + (lid & 3) * 2;
#pragma unroll
                for (int half = 0; half < 2; half++) {
                    int row = mt * 16 + fq + half * 8;
                    *(float2*)&g_pre[dir][gate][row][hc] = make_float2(
                        acc[mt][nt][half * 2 + 0], acc[mt][nt][half * 2 + 1]);
                }
            }
        }

        // ================= barrier: pre ready =================
        __threadfence();
        __syncthreads();
        if (tid == 0) {
            atomicAdd(&g_bar[0][t], 1);
            while (*(volatile int*)&g_bar[0][t] < NBLK) __nanosleep(64);
        }
        __syncthreads();

        // ================= cell phase =================
        {
            float pre[4][4];
#pragma unroll
            for (int g = 0; g < 4; ++g) {
                float4 v = __ldcg((const float4*)&g_pre[dir_c][g][n_c][h_c]);
                pre[g][0] = v.x + xpre[g].x;
                pre[g][1] = v.y + xpre[g].y;
                pre[g][2] = v.z + xpre[g].z;
                pre[g][3] = v.w + xpre[g].w;
            }
#pragma unroll
            for (int j = 0; j < 4; ++j) {
                float f  = sigmf(pre[0][j]);
                float ii = sigmf(pre[1][j]);
                float o  = sigmf(pre[2][j]);
                cc[j] = f * cc[j] + ii * tanhf(pre[3][j]);
                float hn = o * tanhf(cc[j]);
                hr[j] = (m == 0.0f) ? hr[j] : hn;
            }

            // Write h as bf16 hi/lo for next step's A operand
            __nv_bfloat16 hi[4], lo[4];
#pragma unroll
            for (int j = 0; j < 4; ++j) {
                hi[j] = __float2bfloat16_rn(hr[j]);
                lo[j] = __float2bfloat16_rn(hr[j] - __bfloat162float(hi[j]));
            }
            __nv_bfloat162 hp0 = __halves2bfloat162(hi[0], hi[1]);
            __nv_bfloat162 hp1 = __halves2bfloat162(hi[2], hi[3]);
            __nv_bfloat162 lp0 = __halves2bfloat162(lo[0], lo[1]);
            __nv_bfloat162 lp1 = __halves2bfloat162(lo[2], lo[3]);
            *(uint2*)&g_hbf_hi[dir_c][n_c][h_c] =
                make_uint2(*(uint32_t*)&hp0, *(uint32_t*)&hp1);
            *(uint2*)&g_hbf_lo[dir_c][n_c][h_c] =
                make_uint2(*(uint32_t*)&lp0, *(uint32_t*)&lp1);

            *(float4*)&out[(((size_t)n_c * SL + pos_c) * 2 + dir_c) * HH + h_c] =
                make_float4(hr[0] * m, hr[1] * m, hr[2] * m, hr[3] * m);
            if (t == SL - 1) {
                *(float4*)&out[(size_t)NB * SL * 2 * HH +
                               ((size_t)n_c * 2 + dir_c) * HH + h_c] =
                    make_float4(hr[0], hr[1], hr[2], hr[3]);
            }
        }

        // ================= barrier: h ready =================
        __threadfence();
        __syncthreads();
        if (tid == 0) {
            atomicAdd(&g_bar[1][t], 1);
            while (*(volatile int*)&g_bar[1][t] < NBLK) __nanosleep(64);
        }
        __syncthreads();
    }
}

// ---------------------------------------------------------------------------
// Launch
// ---------------------------------------------------------------------------
extern "C" void kernel_launch(void* const* d_in, const int* in_sizes, int n_in,
                              void* d_out, int out_size) {
    const float* x    = (const float*)d_in[0];   // (32,256,1024)
    const float* mask = (const float*)d_in[1];   // (32,256)
    const float* wih  = (const float*)d_in[2];   // (8,1024,1024)
    const float* whh  = (const float*)d_in[3];   // (8,1024,1024)
    const float* bias = (const float*)d_in[4];   // (8,1,1024)
    float* out = (float*)d_out;

    zero_state_kernel<<<64, 256>>>();
    convert_x_kernel<<<1024, 256>>>(x);
    dim3 wgrid(32, 32, 8);
    convert_w_kernel<<<wgrid, dim3(32, 8)>>>(wih, 0);
    convert_w_kernel<<<wgrid, dim3(32, 8)>>>(whh, 1);

    dim3 ggrid(64, 16, 8);
    gemm_ih_mma_kernel<<<ggrid, 256>>>(bias);

    bilstm_persistent_mma<<<NBLK, 128>>>(mask, out);
}

// round 8
// speedup vs baseline: 1.7776x; 1.7776x over previous
#include <cuda_runtime.h>
#include <cuda_bf16.h>
#include <math.h>
#include <cstdint>

// Problem constants
#define NB   32      // batch
#define SL   256     // sequence length
#define DD   1024    // input dim
#define HH   1024    // hidden dim
#define NBLK 128     // persistent blocks (2 dir * 64 hc-tiles of 16)

// ---------------------------------------------------------------------------
// Scratch (device globals)
// ---------------------------------------------------------------------------
__device__ float g_xh[(size_t)8 * SL * NB * HH];   // 268 MB: xh[g][s][n][h]
__device__ int   g_bar[SL];                        // grid barrier counters
// bf16 split operands for the input GEMM
__device__ __nv_bfloat16 g_xa_hi[(size_t)NB * SL * DD];
__device__ __nv_bfloat16 g_xa_lo[(size_t)NB * SL * DD];
__device__ __nv_bfloat16 g_wt_hi[(size_t)8 * HH * DD];   // W_ih [g][n][k]
__device__ __nv_bfloat16 g_wt_lo[(size_t)8 * HH * DD];
// bf16 split operands for the recurrence
__device__ __nv_bfloat16 g_wr_hi[(size_t)8 * HH * DD];   // W_hh [g][n][k]
__device__ __nv_bfloat16 g_wr_lo[(size_t)8 * HH * DD];
// h state, double-buffered by step parity
__device__ __nv_bfloat16 g_hbf_hi[2][2][NB][HH];         // [par][dir][n][k]
__device__ __nv_bfloat16 g_hbf_lo[2][2][NB][HH];

__device__ __forceinline__ float sigmf(float v) {
    return 1.0f / (1.0f + expf(-v));
}

// mma.sync m16n8k16 bf16, fp32 accumulate
__device__ __forceinline__ void mma16816(float* c, const uint32_t* a,
                                         const uint32_t* b) {
    asm volatile(
        "mma.sync.aligned.m16n8k16.row.col.f32.bf16.bf16.f32 "
        "{%0,%1,%2,%3}, {%4,%5,%6,%7}, {%8,%9}, {%0,%1,%2,%3};"
        : "+f"(c[0]), "+f"(c[1]), "+f"(c[2]), "+f"(c[3])
        : "r"(a[0]), "r"(a[1]), "r"(a[2]), "r"(a[3]), "r"(b[0]), "r"(b[1]));
}

__device__ __forceinline__ void cp_async16(uint32_t sdst, const void* gsrc) {
    asm volatile("cp.async.cg.shared.global [%0], [%1], 16;"
                 :: "r"(sdst), "l"(gsrc));
}
__device__ __forceinline__ void cp_commit() {
    asm volatile("cp.async.commit_group;" ::: "memory");
}
__device__ __forceinline__ void cp_wait1() {
    asm volatile("cp.async.wait_group 1;" ::: "memory");
}
__device__ __forceinline__ void cp_wait0() {
    asm volatile("cp.async.wait_group 0;" ::: "memory");
}
__device__ __forceinline__ uint32_t smem_u32(const void* p) {
    uint32_t a;
    asm("{ .reg .u64 t; cvta.to.shared.u64 t, %1; cvt.u32.u64 %0, t; }"
        : "=r"(a) : "l"(p));
    return a;
}

// ---------------------------------------------------------------------------
// Kernel 0: zero init of h state (both parities) and barrier counters
// ---------------------------------------------------------------------------
__global__ void zero_state_kernel() {
    int idx = blockIdx.x * blockDim.x + threadIdx.x;
    float* h1 = (float*)&g_hbf_hi[0][0][0][0];
    float* h2 = (float*)&g_hbf_lo[0][0][0][0];
    int total = 2 * 2 * NB * HH / 2;      // bf16 pairs as floats
    for (int i = idx; i < total; i += gridDim.x * blockDim.x) {
        h1[i] = 0.0f;
        h2[i] = 0.0f;
    }
    for (int i = idx; i < SL; i += gridDim.x * blockDim.x) g_bar[i] = 0;
}

// ---------------------------------------------------------------------------
// Kernel A: convert x -> bf16 hi/lo
// ---------------------------------------------------------------------------
__global__ __launch_bounds__(256)
void convert_x_kernel(const float* __restrict__ x) {
    const size_t total4 = (size_t)NB * SL * DD / 4;
    for (size_t i = blockIdx.x * 256 + threadIdx.x; i < total4;
         i += (size_t)gridDim.x * 256) {
        float4 v = *(const float4*)(x + i * 4);
        __nv_bfloat16 h0 = __float2bfloat16_rn(v.x);
        __nv_bfloat16 h1 = __float2bfloat16_rn(v.y);
        __nv_bfloat16 h2 = __float2bfloat16_rn(v.z);
        __nv_bfloat16 h3 = __float2bfloat16_rn(v.w);
        __nv_bfloat16 l0 = __float2bfloat16_rn(v.x - __bfloat162float(h0));
        __nv_bfloat16 l1 = __float2bfloat16_rn(v.y - __bfloat162float(h1));
        __nv_bfloat16 l2 = __float2bfloat16_rn(v.z - __bfloat162float(h2));
        __nv_bfloat16 l3 = __float2bfloat16_rn(v.w - __bfloat162float(h3));
        __nv_bfloat162 hh0 = __halves2bfloat162(h0, h1);
        __nv_bfloat162 hh1 = __halves2bfloat162(h2, h3);
        __nv_bfloat162 ll0 = __halves2bfloat162(l0, l1);
        __nv_bfloat162 ll1 = __halves2bfloat162(l2, l3);
        *(uint2*)(g_xa_hi + i * 4) = make_uint2(*(uint32_t*)&hh0, *(uint32_t*)&hh1);
        *(uint2*)(g_xa_lo + i * 4) = make_uint2(*(uint32_t*)&ll0, *(uint32_t*)&ll1);
    }
}

// ---------------------------------------------------------------------------
// Kernel B: transpose + convert weights -> [g][n][k] bf16 hi/lo
// ---------------------------------------------------------------------------
__global__ void convert_w_kernel(const float* __restrict__ w, int which) {
    __shared__ float tile[32][33];
    const int g  = blockIdx.z;
    const int k0 = blockIdx.x * 32;
    const int n0 = blockIdx.y * 32;
    const int tx = threadIdx.x, ty = threadIdx.y;   // (32, 8)
    const float* W = w + ((size_t)g << 20);
    __nv_bfloat16* dst_hi = which ? g_wr_hi : g_wt_hi;
    __nv_bfloat16* dst_lo = which ? g_wr_lo : g_wt_lo;
#pragma unroll
    for (int i = 0; i < 4; i++)
        tile[ty + 8 * i][tx] = W[(size_t)(k0 + ty + 8 * i) * HH + n0 + tx];
    __syncthreads();
#pragma unroll
    for (int i = 0; i < 4; i++) {
        float v = tile[tx][ty + 8 * i];
        __nv_bfloat16 hi = __float2bfloat16_rn(v);
        __nv_bfloat16 lo = __float2bfloat16_rn(v - __bfloat162float(hi));
        size_t idx = ((size_t)g << 20) + (size_t)(n0 + ty + 8 * i) * DD + k0 + tx;
        dst_hi[idx] = hi;
        dst_lo[idx] = lo;
    }
}

// ---------------------------------------------------------------------------
// Kernel C: mma.sync bf16x3 input-projection GEMM (proven in R6).
// ---------------------------------------------------------------------------
#define ASTR 40

__global__ __launch_bounds__(256, 2)
void gemm_ih_mma_kernel(const float* __restrict__ bias) {
    __shared__ __nv_bfloat16 As_hi[128][ASTR];
    __shared__ __nv_bfloat16 As_lo[128][ASTR];
    __shared__ __nv_bfloat16 Bs_hi[64][ASTR];
    __shared__ __nv_bfloat16 Bs_lo[64][ASTR];

    const int g   = blockIdx.z;
    const int m0  = blockIdx.x * 128;
    const int n0  = blockIdx.y * 64;
    const int tid = threadIdx.x;
    const int wid = tid >> 5;
    const int lid = tid & 31;
    const int wm  = wid & 3;
    const int wn  = wid >> 2;

    const __nv_bfloat16* a_hi = g_xa_hi;
    const __nv_bfloat16* a_lo = g_xa_lo;
    const __nv_bfloat16* b_hi = g_wt_hi + ((size_t)g << 20);
    const __nv_bfloat16* b_lo = g_wt_lo + ((size_t)g << 20);

    float acc[2][4][4];
#pragma unroll
    for (int mt = 0; mt < 2; mt++)
#pragma unroll
        for (int nt = 0; nt < 4; nt++)
#pragma unroll
            for (int r = 0; r < 4; r++) acc[mt][nt][r] = 0.0f;

    const int fq = lid >> 2;
    const int fk = (lid & 3) * 2;

    for (int k0 = 0; k0 < DD; k0 += 32) {
        __syncthreads();
#pragma unroll
        for (int s = 0; s < 2; s++) {
            int lin = tid + s * 256;
            int row = lin >> 2;
            int kq  = (lin & 3) * 8;
            *(uint4*)&As_hi[row][kq] =
                *(const uint4*)(a_hi + (size_t)(m0 + row) * DD + k0 + kq);
            *(uint4*)&As_lo[row][kq] =
                *(const uint4*)(a_lo + (size_t)(m0 + row) * DD + k0 + kq);
        }
        {
            int row = tid >> 2;
            int kq  = (tid & 3) * 8;
            *(uint4*)&Bs_hi[row][kq] =
                *(const uint4*)(b_hi + (size_t)(n0 + row) * DD + k0 + kq);
            *(uint4*)&Bs_lo[row][kq] =
                *(const uint4*)(b_lo + (size_t)(n0 + row) * DD + k0 + kq);
        }
        __syncthreads();

#pragma unroll
        for (int ks = 0; ks < 32; ks += 16) {
            uint32_t Ah[2][4], Al[2][4], Bh[4][2], Bl[4][2];
#pragma unroll
            for (int mt = 0; mt < 2; mt++) {
                int mb = wm * 32 + mt * 16;
                Ah[mt][0] = *(const uint32_t*)&As_hi[mb + fq][ks + fk];
                Ah[mt][1] = *(const uint32_t*)&As_hi[mb + fq + 8][ks + fk];
                Ah[mt][2] = *(const uint32_t*)&As_hi[mb + fq][ks + fk + 8];
                Ah[mt][3] = *(const uint32_t*)&As_hi[mb + fq + 8][ks + fk + 8];
                Al[mt][0] = *(const uint32_t*)&As_lo[mb + fq][ks + fk];
                Al[mt][1] = *(const uint32_t*)&As_lo[mb + fq + 8][ks + fk];
                Al[mt][2] = *(const uint32_t*)&As_lo[mb + fq][ks + fk + 8];
                Al[mt][3] = *(const uint32_t*)&As_lo[mb + fq + 8][ks + fk + 8];
            }
#pragma unroll
            for (int nt = 0; nt < 4; nt++) {
                int nb = wn * 32 + nt * 8;
                Bh[nt][0] = *(const uint32_t*)&Bs_hi[nb + fq][ks + fk];
                Bh[nt][1] = *(const uint32_t*)&Bs_hi[nb + fq][ks + fk + 8];
                Bl[nt][0] = *(const uint32_t*)&Bs_lo[nb + fq][ks + fk];
                Bl[nt][1] = *(const uint32_t*)&Bs_lo[nb + fq][ks + fk + 8];
            }
#pragma unroll
            for (int mt = 0; mt < 2; mt++)
#pragma unroll
                for (int nt = 0; nt < 4; nt++) {
                    mma16816(acc[mt][nt], Ah[mt], Bh[nt]);
                    mma16816(acc[mt][nt], Ah[mt], Bl[nt]);
                    mma16816(acc[mt][nt], Al[mt], Bh[nt]);
                }
        }
    }

#pragma unroll
    for (int mt = 0; mt < 2; mt++) {
#pragma unroll
        for (int nt = 0; nt < 4; nt++) {
            int col = n0 + wn * 32 + nt * 8 + (lid & 3) * 2;
            float2 bz = *(const float2*)&bias[g * HH + col];
#pragma unroll
            for (int half = 0; half < 2; half++) {
                int row  = m0 + wm * 32 + mt * 16 + fq + half * 8;
                int nidx = row >> 8;
                int s    = row & 255;
                size_t base = ((((size_t)g * SL + s) * NB + nidx) << 10) + col;
                *(float2*)&g_xh[base] = make_float2(
                    acc[mt][nt][half * 2 + 0] + bz.x,
                    acc[mt][nt][half * 2 + 1] + bz.y);
            }
        }
    }
}

// ---------------------------------------------------------------------------
// Kernel D: persistent recurrence. 128 blocks x 256 threads (8 warps).
// Block -> (dir, 16 h-cols across all 4 gates = 64 W rows).
// W_hi resident in smem; W_lo + h(hi/lo) streamed via cp.async ring.
// Warp (kh = wid>>2, nq = wid&3): K-half kh, 16-col slice nq. One grid
// barrier per step; h double-buffered by parity.
// ---------------------------------------------------------------------------
// smem layout (bytes)
#define SM_WHI   0                       // [64][1032] bf16      = 132096
#define SM_ASH   132096                  // [2][2][32][72] bf16  = 18432
#define SM_ASL   (132096 + 18432)        // same                 = 18432
#define SM_WLO   (132096 + 36864)        // [2][2][64][72] bf16  = 36864
#define SM_PART  (132096 + 73728)        // [2][32][64] f32      = 16384
#define SM_TOTAL (132096 + 73728 + 16384)   // 222208

#define WHI_OFF(row, k)           ((size_t)(SM_WHI) + ((row) * 1032 + (k)) * 2)
#define ASH_OFF(s, h, row, k)     ((size_t)(SM_ASH) + ((((s)*2 + (h))*32 + (row))*72 + (k)) * 2)
#define ASL_OFF(s, h, row, k)     ((size_t)(SM_ASL) + ((((s)*2 + (h))*32 + (row))*72 + (k)) * 2)
#define WLO_OFF(s, h, row, k)     ((size_t)(SM_WLO) + ((((s)*2 + (h))*64 + (row))*72 + (k)) * 2)
#define PART_OFF(kh, row, col)    ((size_t)(SM_PART) + (((kh)*32 + (row))*64 + (col)) * 4)

__global__ __launch_bounds__(256, 1)
void bilstm_persistent_mma2(const float* __restrict__ mask,
                            float* __restrict__ out) {
    extern __shared__ char smem[];
    const uint32_t sb = smem_u32(smem);

    const int bid = blockIdx.x;
    const int dir = bid & 1;
    const int ht  = bid >> 1;             // 0..63 (16-col tile)
    const int tid = threadIdx.x;
    const int wid = tid >> 5;
    const int lid = tid & 31;
    const int kh  = wid >> 2;             // K half
    const int nq  = wid & 3;              // 16-col slice
    const int fq  = lid >> 2;
    const int fk  = (lid & 3) * 2;

    const __nv_bfloat16* WhiG = g_wr_hi + (((size_t)(dir * 4)) << 20);
    const __nv_bfloat16* WloG = g_wr_lo + (((size_t)(dir * 4)) << 20);

    // ---- load resident W_hi (64 rows x 1024 k) ----
#pragma unroll
    for (int s2 = 0; s2 < 32; s2++) {
        int lin = tid + s2 * 256;          // 0..8191
        int row = lin >> 7;                // 64 rows, 128 16B-segs each
        int kq  = (lin & 127) * 8;
        int gg  = row >> 4, j = row & 15;
        uint4 v = *(const uint4*)(WhiG + (((size_t)gg) << 20) +
                                  (size_t)(ht * 16 + j) * 1024 + kq);
        *(uint4*)(smem + WHI_OFF(row, kq)) = v;
    }
    __syncthreads();

    // Cell assignment: thread -> (n, 2 h-cols)
    const int n_c  = tid >> 3;             // 0..31
    const int jj   = (tid & 7) * 2;        // 0..14
    const int hcol = ht * 16 + jj;         // global h column (pair)
    float cc[2] = {0.f, 0.f};
    float hr[2] = {0.f, 0.f};
    const float* mrow = mask + n_c * SL;

    for (int t = 0; t < SL; t++) {
        const int par = t & 1;
        const int pos = dir ? (SL - 1 - t) : t;
        const __nv_bfloat16* AhiG = &g_hbf_hi[par][dir][0][0];
        const __nv_bfloat16* AloG = &g_hbf_lo[par][dir][0][0];

        // Prefetch cell xh + mask (DRAM latency hidden under GEMM)
        float2 xpre[4];
#pragma unroll
        for (int g = 0; g < 4; ++g)
            xpre[g] = __ldcg((const float2*)&g_xh[
                ((((size_t)(dir * 4 + g) * SL + pos) * NB + n_c) << 10) + hcol]);
        const float m = mrow[pos];

        // ---- stage chunks 0 and 1 ----
#pragma unroll
        for (int pc = 0; pc < 2; pc++) {
            // A segs: hi/lo x 2 halves x 32 rows x 8 segs = 1024 -> 4/thread
#pragma unroll
            for (int s2 = 0; s2 < 4; s2++) {
                int id  = tid + s2 * 256;
                int arr = id >> 9;
                int rem = id & 511;
                int hh  = rem >> 8;
                int r2  = rem & 255;
                int row = r2 >> 3;
                int kq  = (r2 & 7) * 8;
                const __nv_bfloat16* src = (arr ? AloG : AhiG) +
                    (size_t)row * HH + hh * 512 + pc * 64 + kq;
                uint32_t dst = sb + (uint32_t)(arr ? ASL_OFF(pc, hh, row, kq)
                                                   : ASH_OFF(pc, hh, row, kq));
                cp_async16(dst, src);
            }
            // W_lo segs: 2 halves x 64 rows x 8 segs = 1024 -> 4/thread
#pragma unroll
            for (int s2 = 0; s2 < 4; s2++) {
                int id  = tid + s2 * 256;
                int hh  = id >> 9;
                int r2  = id & 511;
                int row = r2 >> 3;
                int kq  = (r2 & 7) * 8;
                int gg  = row >> 4, j = row & 15;
                const __nv_bfloat16* src = WloG + (((size_t)gg) << 20) +
                    (size_t)(ht * 16 + j) * 1024 + hh * 512 + pc * 64 + kq;
                uint32_t dst = sb + (uint32_t)WLO_OFF(pc, hh, row, kq);
                cp_async16(dst, src);
            }
            cp_commit();
        }

        float acc[2][2][4];
#pragma unroll
        for (int mt = 0; mt < 2; mt++)
#pragma unroll
            for (int nt = 0; nt < 2; nt++)
#pragma unroll
                for (int r = 0; r < 4; r++) acc[mt][nt][r] = 0.0f;

        // ---- main chunk loop: 8 chunks of 64k per K-half ----
        for (int c = 0; c < 8; c++) {
            if (c < 7) cp_wait1(); else cp_wait0();
            __syncthreads();
            const int s = c & 1;

#pragma unroll
            for (int ks = 0; ks < 4; ks++) {
                const int kr = ks * 16;                       // ring k
                const int kg = kh * 512 + c * 64 + kr;        // resident k
                uint32_t Ah[2][4], Al[2][4];
#pragma unroll
                for (int mt = 0; mt < 2; mt++) {
                    int rb = mt * 16 + fq;
                    Ah[mt][0] = *(const uint32_t*)(smem + ASH_OFF(s, kh, rb,     kr + fk));
                    Ah[mt][1] = *(const uint32_t*)(smem + ASH_OFF(s, kh, rb + 8, kr + fk));
                    Ah[mt][2] = *(const uint32_t*)(smem + ASH_OFF(s, kh, rb,     kr + fk + 8));
                    Ah[mt][3] = *(const uint32_t*)(smem + ASH_OFF(s, kh, rb + 8, kr + fk + 8));
                    Al[mt][0] = *(const uint32_t*)(smem + ASL_OFF(s, kh, rb,     kr + fk));
                    Al[mt][1] = *(const uint32_t*)(smem + ASL_OFF(s, kh, rb + 8, kr + fk));
                    Al[mt][2] = *(const uint32_t*)(smem + ASL_OFF(s, kh, rb,     kr + fk + 8));
                    Al[mt][3] = *(const uint32_t*)(smem + ASL_OFF(s, kh, rb + 8, kr + fk + 8));
                }
#pragma unroll
                for (int nt = 0; nt < 2; nt++) {
                    int rB = nq * 16 + nt * 8 + fq;
                    uint32_t Bh[2], Bl[2];
                    Bh[0] = *(const uint32_t*)(smem + WHI_OFF(rB, kg + fk));
                    Bh[1] = *(const uint32_t*)(smem + WHI_OFF(rB, kg + fk + 8));
                    Bl[0] = *(const uint32_t*)(smem + WLO_OFF(s, kh, rB, kr + fk));
                    Bl[1] = *(const uint32_t*)(smem + WLO_OFF(s, kh, rB, kr + fk + 8));
                    mma16816(acc[0][nt], Ah[0], Bh);
                    mma16816(acc[1][nt], Ah[1], Bh);
                    mma16816(acc[0][nt], Ah[0], Bl);
                    mma16816(acc[1][nt], Ah[1], Bl);
                    mma16816(acc[0][nt], Al[0], Bh);
                    mma16816(acc[1][nt], Al[1], Bh);
                }
            }
            __syncthreads();

            if (c + 2 < 8) {
                const int nc = c + 2;
                const int sl = c & 1;
#pragma unroll
                for (int s2 = 0; s2 < 4; s2++) {
                    int id  = tid + s2 * 256;
                    int arr = id >> 9;
                    int rem = id & 511;
                    int hh  = rem >> 8;
                    int r2  = rem & 255;
                    int row = r2 >> 3;
                    int kq  = (r2 & 7) * 8;
                    const __nv_bfloat16* src = (arr ? AloG : AhiG) +
                        (size_t)row * HH + hh * 512 + nc * 64 + kq;
                    uint32_t dst = sb + (uint32_t)(arr ? ASL_OFF(sl, hh, row, kq)
                                                       : ASH_OFF(sl, hh, row, kq));
                    cp_async16(dst, src);
                }
#pragma unroll
                for (int s2 = 0; s2 < 4; s2++) {
                    int id  = tid + s2 * 256;
                    int hh  = id >> 9;
                    int r2  = id & 511;
                    int row = r2 >> 3;
                    int kq  = (r2 & 7) * 8;
                    int gg  = row >> 4, j = row & 15;
                    const __nv_bfloat16* src = WloG + (((size_t)gg) << 20) +
                        (size_t)(ht * 16 + j) * 1024 + hh * 512 + nc * 64 + kq;
                    uint32_t dst = sb + (uint32_t)WLO_OFF(sl, hh, row, kq);
                    cp_async16(dst, src);
                }
                cp_commit();
            }
        }

        // ---- write partials to smem ----
#pragma unroll
        for (int mt = 0; mt < 2; mt++)
#pragma unroll
            for (int nt = 0; nt < 2; nt++) {
                int col = nq * 16 + nt * 8 + (lid & 3) * 2;
                *(float2*)(smem + PART_OFF(kh, mt * 16 + fq, col)) =
                    make_float2(acc[mt][nt][0], acc[mt][nt][1]);
                *(float2*)(smem + PART_OFF(kh, mt * 16 + fq + 8, col)) =
                    make_float2(acc[mt][nt][2], acc[mt][nt][3]);
            }
        __syncthreads();

        // ---- cell phase (block-local) ----
        {
            float pre[4][2];
#pragma unroll
            for (int g = 0; g < 4; ++g) {
                float2 p0 = *(const float2*)(smem + PART_OFF(0, n_c, g * 16 + jj));
                float2 p1 = *(const float2*)(smem + PART_OFF(1, n_c, g * 16 + jj));
                pre[g][0] = xpre[g].x + p0.x + p1.x;
                pre[g][1] = xpre[g].y + p0.y + p1.y;
            }
#pragma unroll
            for (int j = 0; j < 2; ++j) {
                float f  = sigmf(pre[0][j]);
                float ii = sigmf(pre[1][j]);
                float o  = sigmf(pre[2][j]);
                cc[j] = f * cc[j] + ii * tanhf(pre[3][j]);
                float hn = o * tanhf(cc[j]);
                hr[j] = (m == 0.0f) ? hr[j] : hn;
            }

            __nv_bfloat16 hi0 = __float2bfloat16_rn(hr[0]);
            __nv_bfloat16 hi1 = __float2bfloat16_rn(hr[1]);
            __nv_bfloat16 lo0 = __float2bfloat16_rn(hr[0] - __bfloat162float(hi0));
            __nv_bfloat16 lo1 = __float2bfloat16_rn(hr[1] - __bfloat162float(hi1));
            __nv_bfloat162 hp = __halves2bfloat162(hi0, hi1);
            __nv_bfloat162 lp = __halves2bfloat162(lo0, lo1);
            *(uint32_t*)&g_hbf_hi[par ^ 1][dir][n_c][hcol] = *(uint32_t*)&hp;
            *(uint32_t*)&g_hbf_lo[par ^ 1][dir][n_c][hcol] = *(uint32_t*)&lp;

            *(float2*)&out[(((size_t)n_c * SL + pos) * 2 + dir) * HH + hcol] =
                make_float2(hr[0] * m, hr[1] * m);
            if (t == SL - 1) {
                *(float2*)&out[(size_t)NB * SL * 2 * HH +
                               ((size_t)n_c * 2 + dir) * HH + hcol] =
                    make_float2(hr[0], hr[1]);
            }
        }

        // ---- single grid barrier: h(t) ready ----
        __threadfence();
        __syncthreads();
        if (tid == 0) {
            atomicAdd(&g_bar[t], 1);
            while (*(volatile int*)&g_bar[t] < NBLK) __nanosleep(64);
        }
        __syncthreads();
    }
}

// ---------------------------------------------------------------------------
// Launch
// ---------------------------------------------------------------------------
extern "C" void kernel_launch(void* const* d_in, const int* in_sizes, int n_in,
                              void* d_out, int out_size) {
    const float* x    = (const float*)d_in[0];   // (32,256,1024)
    const float* mask = (const float*)d_in[1];   // (32,256)
    const float* wih  = (const float*)d_in[2];   // (8,1024,1024)
    const float* whh  = (const float*)d_in[3];   // (8,1024,1024)
    const float* bias = (const float*)d_in[4];   // (8,1,1024)
    float* out = (float*)d_out;

    cudaFuncSetAttribute(bilstm_persistent_mma2,
                         cudaFuncAttributeMaxDynamicSharedMemorySize,
                         SM_TOTAL);

    zero_state_kernel<<<64, 256>>>();
    convert_x_kernel<<<1024, 256>>>(x);
    dim3 wgrid(32, 32, 8);
    convert_w_kernel<<<wgrid, dim3(32, 8)>>>(wih, 0);
    convert_w_kernel<<<wgrid, dim3(32, 8)>>>(whh, 1);

    dim3 ggrid(64, 16, 8);
    gemm_ih_mma_kernel<<<ggrid, 256>>>(bias);

    bilstm_persistent_mma2<<<NBLK, 256, SM_TOTAL>>>(mask, out);
}